// round 4
// baseline (speedup 1.0000x reference)
#include <cuda_runtime.h>
#include <math_constants.h>

#define BSZ   64
#define NGEN  128
#define NCLS  30
#define SEQ   2048
#define G     16
#define TGOLD (BSZ * G)                              // 1024
#define COST_ELEMS ((size_t)BSZ * NGEN * TGOLD)      // 8388608
#define ROWS_PER_BLK 8

struct Ptrs {
    const float* pos[8];   // 8 positional logit tensors [BSZ*NGEN, SEQ]
    const int*   gidx[8];  // 8 gold index arrays [TGOLD]
};

// ---------------------------------------------------------------------------
// Cost kernel: one block per 8 consecutive (b,n) rows. 256 threads.
// Gather indices in registers for the whole block; 2 barriers/dist; prefetch
// across (row,dist); no max-subtraction (N(0,1) logits, shift-invariant).
// ---------------------------------------------------------------------------
__global__ __launch_bounds__(256)
void cost_kernel(const float* __restrict__ prel, const int* __restrict__ grel,
                 Ptrs ptrs, float* __restrict__ out) {
    const int row0 = blockIdx.x * ROWS_PER_BLK;
    const int tid  = threadIdx.x;
    const int w    = tid >> 5;
    const int lane = tid & 31;

    __shared__ float probs[SEQ];           // 8 KB
    __shared__ float relp[ROWS_PER_BLK][32];
    __shared__ float red[8];

    int gr[4];
    int gi[8][4];
    #pragma unroll
    for (int t = 0; t < 4; t++) gr[t] = grel[tid + 256 * t];
    #pragma unroll
    for (int d = 0; d < 8; d++)
        #pragma unroll
        for (int t = 0; t < 4; t++) gi[d][t] = ptrs.gidx[d][tid + 256 * t];

    // rel-class softmax for all 8 rows: warp w handles row row0+w
    {
        float e = (lane < NCLS) ? __expf(prel[(size_t)(row0 + w) * NCLS + lane]) : 0.f;
        float s = e;
        #pragma unroll
        for (int o = 16; o; o >>= 1) s += __shfl_xor_sync(0xffffffffu, s, o);
        if (lane < NCLS) relp[w][lane] = e / s;
    }
    __syncthreads();

    const float4* r4 = (const float4*)(ptrs.pos[0] + (size_t)row0 * SEQ);
    float4 v0 = r4[tid];
    float4 v1 = r4[tid + 256];

    #pragma unroll 1
    for (int r = 0; r < ROWS_PER_BLK; r++) {
        float acc0 = relp[r][gr[0]];
        float acc1 = relp[r][gr[1]];
        float acc2 = relp[r][gr[2]];
        float acc3 = relp[r][gr[3]];

        #pragma unroll
        for (int d = 0; d < 8; d++) {
            float4 n0, n1;
            if (d < 7) {
                const float4* nx = (const float4*)(ptrs.pos[d + 1] + (size_t)(row0 + r) * SEQ);
                n0 = nx[tid]; n1 = nx[tid + 256];
            } else if (r < ROWS_PER_BLK - 1) {
                const float4* nx = (const float4*)(ptrs.pos[0] + (size_t)(row0 + r + 1) * SEQ);
                n0 = nx[tid]; n1 = nx[tid + 256];
            }

            float4 e0, e1;
            e0.x = __expf(v0.x); e0.y = __expf(v0.y); e0.z = __expf(v0.z); e0.w = __expf(v0.w);
            e1.x = __expf(v1.x); e1.y = __expf(v1.y); e1.z = __expf(v1.z); e1.w = __expf(v1.w);
            ((float4*)probs)[tid]       = e0;
            ((float4*)probs)[tid + 256] = e1;

            float lsum = (e0.x + e0.y) + (e0.z + e0.w) + (e1.x + e1.y) + (e1.z + e1.w);
            #pragma unroll
            for (int o = 16; o; o >>= 1) lsum += __shfl_xor_sync(0xffffffffu, lsum, o);
            if (lane == 0) red[w] = lsum;
            __syncthreads();

            float s = ((red[0] + red[1]) + (red[2] + red[3]))
                    + ((red[4] + red[5]) + (red[6] + red[7]));
            float inv = 1.0f / s;

            acc0 += probs[gi[d][0]] * inv;
            acc1 += probs[gi[d][1]] * inv;
            acc2 += probs[gi[d][2]] * inv;
            acc3 += probs[gi[d][3]] * inv;
            __syncthreads();

            v0 = n0; v1 = n1;
        }

        const size_t base = (size_t)(row0 + r) * TGOLD;
        out[base + tid]       = -acc0;
        out[base + tid + 256] = -acc1;
        out[base + tid + 512] = -acc2;
        out[base + tid + 768] = -acc3;
    }
}

// ---------------------------------------------------------------------------
// LSA helpers: monotone u64 key for f64 (order-isomorphic, no NaN here),
// exact inverse, and redux.sync.min.u32.
// ---------------------------------------------------------------------------
__device__ __forceinline__ unsigned long long dkey(double x) {
    long long b = __double_as_longlong(x);
    // negative -> ~bits (descending magnitude), positive -> bits | msb
    return (unsigned long long)(b ^ ((b >> 63) | 0x8000000000000000ll));
}
__device__ __forceinline__ double dunkey(unsigned long long k) {
    long long b;
    if (k & 0x8000000000000000ull) b = (long long)(k ^ 0x8000000000000000ull);
    else                           b = (long long)(~k);
    return __longlong_as_double(b);
}
__device__ __forceinline__ unsigned redux_min_u32(unsigned x) {
    unsigned r;
    asm volatile("redux.sync.min.u32 %0, %1, 0xffffffff;" : "=r"(r) : "r"(x));
    return r;
}

// ---------------------------------------------------------------------------
// LSA: one warp per example. Exact Jonker-Volgenant (e-maxx form) in f64,
// v initialized to ZERO (required for the rectangular LP: v_j <= 0 with
// CS "v_j<0 => column matched" holds only with this init). Argmin done with
// integer keys + redux.sync.min; delta reconstructed bit-exactly.
// C[i][j] = cost[b, j, b*G + i]  (16 x 128 transposed view).
// ---------------------------------------------------------------------------
__global__ __launch_bounds__(32)
void lsa_kernel(const float* __restrict__ cost, float* __restrict__ rows_out,
                float* __restrict__ cols_out) {
    const int b = blockIdx.x;
    const int lane = threadIdx.x;

    __shared__ float  Cf[G * NGEN];   // 8 KB
    __shared__ double u[G + 1];
    __shared__ int    p[NGEN + 1];
    __shared__ int    way[NGEN + 1];
    __shared__ int    col[G];

    // Coalesced load: per column j, 16 i-values are 64 contiguous bytes
    for (int j = lane; j < NGEN; j += 32) {
        const float4* src = (const float4*)(cost + ((size_t)(b * NGEN + j)) * TGOLD + b * G);
        #pragma unroll
        for (int q = 0; q < 4; q++) {
            float4 f = src[q];
            Cf[(q * 4 + 0) * NGEN + j] = f.x;
            Cf[(q * 4 + 1) * NGEN + j] = f.y;
            Cf[(q * 4 + 2) * NGEN + j] = f.z;
            Cf[(q * 4 + 3) * NGEN + j] = f.w;
        }
    }
    for (int k = lane; k <= NGEN; k += 32) p[k] = 0;
    if (lane <= G) u[lane] = 0.0;
    __syncwarp();

    double vreg[4];                  // v[j], j = 1 + lane + 32*t  (ZERO init!)
    #pragma unroll
    for (int t = 0; t < 4; t++) vreg[t] = 0.0;

    for (int i = 1; i <= G; i++) {
        double minv[4];
        #pragma unroll
        for (int t = 0; t < 4; t++) minv[t] = (double)INFINITY;
        unsigned usedm = 0;
        if (lane == 0) p[0] = i;
        __syncwarp();

        int j0 = 0;
        while (true) {
            if (j0 > 0 && ((j0 - 1) & 31) == lane) usedm |= 1u << ((j0 - 1) >> 5);

            int i0 = p[j0];
            double uu = u[i0];
            const float* Crow = &Cf[(i0 - 1) * NGEN];

            unsigned long long bestk = 0xFFFFFFFFFFFFFFFFull;
            unsigned bestj = 0xFFFFFFFFu;
            #pragma unroll
            for (int t = 0; t < 4; t++) {
                if (!(usedm & (1u << t))) {
                    int j = 1 + lane + t * 32;
                    double cur = (double)Crow[j - 1] - uu - vreg[t];
                    unsigned long long kc = dkey(cur);
                    unsigned long long km = dkey(minv[t]);
                    if (kc < km) { minv[t] = cur; way[j] = j0; km = kc; }
                    // ascending j within lane: strict < keeps smallest j
                    if (km < bestk) { bestk = km; bestj = (unsigned)j; }
                }
            }
            // warp argmin via 3 redux.min: hi bits, lo bits, then smallest j
            unsigned hi = (unsigned)(bestk >> 32);
            unsigned lo = (unsigned)(bestk & 0xFFFFFFFFull);
            unsigned hmin = redux_min_u32(hi);
            unsigned lo_in = (hi == hmin) ? lo : 0xFFFFFFFFu;
            unsigned lmin = redux_min_u32(lo_in);
            unsigned j_in = (hi == hmin && lo == lmin) ? bestj : 0xFFFFFFFFu;
            unsigned j1   = redux_min_u32(j_in);

            double delta = dunkey(((unsigned long long)hmin << 32) | lmin);

            #pragma unroll
            for (int t = 0; t < 4; t++) {
                if (usedm & (1u << t)) {
                    int j = 1 + lane + t * 32;
                    u[p[j]] += delta;      // distinct rows across used cols
                    vreg[t] -= delta;
                } else {
                    minv[t] -= delta;
                }
            }
            if (lane == 0) u[p[0]] += delta;
            __syncwarp();

            j0 = (int)j1;
            if (p[j0] == 0) break;
        }
        // augment along 'way'
        if (lane == 0) {
            int jj = j0;
            while (jj) { int jp = way[jj]; p[jj] = p[jp]; jj = jp; }
        }
        __syncwarp();
    }

    if (lane == 0) {
        for (int j = 1; j <= NGEN; j++)
            if (p[j]) col[p[j] - 1] = j - 1;
    }
    __syncwarp();

    // transposed return: order = argsort(col); rows = col[order], cols = order
    if (lane < G) {
        int c = col[lane];
        int rank = 0;
        #pragma unroll
        for (int r2 = 0; r2 < G; r2++) rank += (col[r2] < c) ? 1 : 0;
        rows_out[b * G + rank] = (float)c;
        cols_out[b * G + rank] = (float)lane;
    }
}

// ---------------------------------------------------------------------------
// Launch
// ---------------------------------------------------------------------------
extern "C" void kernel_launch(void* const* d_in, const int* in_sizes, int n_in,
                              void* d_out, int out_size) {
    const float* prel = (const float*)d_in[0];
    Ptrs ptrs;
    for (int d = 0; d < 8; d++) ptrs.pos[d]  = (const float*)d_in[1 + d];
    const int* grel = (const int*)d_in[9];
    for (int d = 0; d < 8; d++) ptrs.gidx[d] = (const int*)d_in[10 + d];

    float* out = (float*)d_out;

    cost_kernel<<<(BSZ * NGEN) / ROWS_PER_BLK, 256>>>(prel, grel, ptrs, out);

    float* rows_out = out + COST_ELEMS;
    float* cols_out = rows_out + (size_t)BSZ * G;
    lsa_kernel<<<BSZ, 32>>>(out, rows_out, cols_out);
}

// round 5
// speedup vs baseline: 1.8514x; 1.8514x over previous
#include <cuda_runtime.h>
#include <math_constants.h>

#define BSZ   64
#define NGEN  128
#define NCLS  30
#define SEQ   2048
#define G     16
#define TGOLD (BSZ * G)                              // 1024
#define COST_ELEMS ((size_t)BSZ * NGEN * TGOLD)      // 8388608

struct Ptrs {
    const float* pos[8];   // 8 positional logit tensors [BSZ*NGEN, SEQ]
    const int*   gidx[8];  // 8 gold index arrays [TGOLD]
};

// ---------------------------------------------------------------------------
// Cost kernel: one block per (b,n) row, 256 threads, register accumulators,
// double-buffered probs/red -> ONE barrier per distribution, prefetch across
// distributions. No max-subtraction (N(0,1) logits; softmax shift-invariant).
// Arithmetic identical to the R2 kernel (bit-identical cost output).
// ---------------------------------------------------------------------------
__global__ __launch_bounds__(256)
void cost_kernel(const float* __restrict__ prel, const int* __restrict__ grel,
                 Ptrs ptrs, float* __restrict__ out) {
    const int row = blockIdx.x;
    const int tid = threadIdx.x;
    const int w   = tid >> 5;
    const int lane = tid & 31;

    __shared__ float probs[2][SEQ];        // 16 KB
    __shared__ float relp[NCLS];
    __shared__ float red[2][8];

    // Issue dist-0 loads as early as possible
    const float4* r4 = (const float4*)(ptrs.pos[0] + (size_t)row * SEQ);
    float4 v0 = r4[tid];
    float4 v1 = r4[tid + 256];

    // warp 0: rel-class softmax (30 classes)
    if (tid < 32) {
        float e = (lane < NCLS) ? __expf(prel[(size_t)row * NCLS + lane]) : 0.f;
        float s = e;
        #pragma unroll
        for (int o = 16; o; o >>= 1) s += __shfl_xor_sync(0xffffffffu, s, o);
        if (lane < NCLS) relp[lane] = e / s;
    }
    __syncthreads();

    float acc0 = relp[grel[tid]];
    float acc1 = relp[grel[tid + 256]];
    float acc2 = relp[grel[tid + 512]];
    float acc3 = relp[grel[tid + 768]];

    #pragma unroll
    for (int d = 0; d < 8; d++) {
        const int pb = d & 1;
        // prefetch next distribution
        float4 n0, n1;
        if (d < 7) {
            const float4* nx = (const float4*)(ptrs.pos[d + 1] + (size_t)row * SEQ);
            n0 = nx[tid]; n1 = nx[tid + 256];
        }
        const int* __restrict__ gi = ptrs.gidx[d];
        int g0 = gi[tid], g1 = gi[tid + 256], g2 = gi[tid + 512], g3 = gi[tid + 768];

        float4 e0, e1;
        e0.x = __expf(v0.x); e0.y = __expf(v0.y); e0.z = __expf(v0.z); e0.w = __expf(v0.w);
        e1.x = __expf(v1.x); e1.y = __expf(v1.y); e1.z = __expf(v1.z); e1.w = __expf(v1.w);
        ((float4*)probs[pb])[tid]       = e0;
        ((float4*)probs[pb])[tid + 256] = e1;

        float lsum = (e0.x + e0.y) + (e0.z + e0.w) + (e1.x + e1.y) + (e1.z + e1.w);
        #pragma unroll
        for (int o = 16; o; o >>= 1) lsum += __shfl_xor_sync(0xffffffffu, lsum, o);
        if (lane == 0) red[pb][w] = lsum;
        __syncthreads();                   // probs[pb] + red[pb] visible

        float s = ((red[pb][0] + red[pb][1]) + (red[pb][2] + red[pb][3]))
                + ((red[pb][4] + red[pb][5]) + (red[pb][6] + red[pb][7]));
        float inv = 1.0f / s;

        acc0 += probs[pb][g0] * inv;
        acc1 += probs[pb][g1] * inv;
        acc2 += probs[pb][g2] * inv;
        acc3 += probs[pb][g3] * inv;
        // no second barrier: next dist writes the OTHER buffer; the overwrite
        // of THIS buffer (d+2) is ordered behind barrier d+1.

        v0 = n0; v1 = n1;
    }

    const size_t base = (size_t)row * TGOLD;
    out[base + tid]       = -acc0;
    out[base + tid + 256] = -acc1;
    out[base + tid + 512] = -acc2;
    out[base + tid + 768] = -acc3;
}

// ---------------------------------------------------------------------------
// Order-isomorphic u64 key for f64 (no NaN here) + exact inverse + redux.min
// ---------------------------------------------------------------------------
__device__ __forceinline__ unsigned long long dkey(double x) {
    long long b = __double_as_longlong(x);
    return (unsigned long long)(b ^ ((b >> 63) | 0x8000000000000000ll));
}
__device__ __forceinline__ double dunkey(unsigned long long k) {
    long long b;
    if (k & 0x8000000000000000ull) b = (long long)(k ^ 0x8000000000000000ull);
    else                           b = (long long)(~k);
    return __longlong_as_double(b);
}
__device__ __forceinline__ unsigned redux_min_u32(unsigned x) {
    unsigned r;
    asm volatile("redux.sync.min.u32 %0, %1, 0xffffffff;" : "=r"(r) : "r"(x));
    return r;
}

// ---------------------------------------------------------------------------
// LSA: one warp per example. Classic LAPJV shortest-augmenting-path with
// DEFERRED potential updates: the Dijkstra inner loop is register-only
// (dist/pred/v/scan per-lane; only broadcast LDS of y[j*] and C[i1][j*]).
// v starts at 0 and only decreases -> rectangular dual feasibility holds.
// f64 path arithmetic; argmin via integer keys + 3x redux.min (exact,
// smallest-j tie-break). C[i][j] = cost[b, j, b*G + i] (16 x 128 view).
// ---------------------------------------------------------------------------
__global__ __launch_bounds__(32)
void lsa_kernel(const float* __restrict__ cost, float* __restrict__ rows_out,
                float* __restrict__ cols_out) {
    const int b = blockIdx.x;
    const int lane = threadIdx.x;

    __shared__ float Cf[G * NGEN];   // 8 KB
    __shared__ int   x[G];           // row -> col
    __shared__ int   y[NGEN];        // col -> row (-1 free)

    for (int j = lane; j < NGEN; j += 32) {
        const float4* src = (const float4*)(cost + ((size_t)(b * NGEN + j)) * TGOLD + b * G);
        #pragma unroll
        for (int q = 0; q < 4; q++) {
            float4 f = src[q];
            Cf[(q * 4 + 0) * NGEN + j] = f.x;
            Cf[(q * 4 + 1) * NGEN + j] = f.y;
            Cf[(q * 4 + 2) * NGEN + j] = f.z;
            Cf[(q * 4 + 3) * NGEN + j] = f.w;
        }
        y[j] = -1;
    }
    __syncwarp();

    double vreg[4];                  // v[j], j = lane + 32*t  (ZERO init)
    #pragma unroll
    for (int t = 0; t < 4; t++) vreg[t] = 0.0;

    for (int f = 0; f < G; f++) {
        double dreg[4];
        int    pr[4];
        #pragma unroll
        for (int t = 0; t < 4; t++) {
            dreg[t] = (double)Cf[f * NGEN + lane + 32 * t] - vreg[t];
            pr[t] = f;
        }
        unsigned scan = 0;
        int jmin;
        double mu;

        while (true) {
            // per-lane best among unscanned (ascending j: strict < keeps min j)
            unsigned long long bestk = 0xFFFFFFFFFFFFFFFFull;
            unsigned bestj = 0xFFFFFFFFu;
            #pragma unroll
            for (int t = 0; t < 4; t++) {
                if (!((scan >> t) & 1u)) {
                    unsigned long long k = dkey(dreg[t]);
                    if (k < bestk) { bestk = k; bestj = (unsigned)(lane + 32 * t); }
                }
            }
            // warp argmin: hi32 -> lo32 -> smallest j
            unsigned hi = (unsigned)(bestk >> 32);
            unsigned lo = (unsigned)bestk;
            unsigned hmin = redux_min_u32(hi);
            unsigned lmin = redux_min_u32((hi == hmin) ? lo : 0xFFFFFFFFu);
            unsigned j1   = redux_min_u32((hi == hmin && lo == lmin) ? bestj
                                                                     : 0xFFFFFFFFu);
            mu = dunkey(((unsigned long long)hmin << 32) | lmin);
            jmin = (int)j1;

            const int tt = jmin >> 5, sl = jmin & 31;
            if (sl == lane) scan |= 1u << tt;

            int i1 = y[jmin];                       // broadcast LDS
            if (i1 < 0) break;

            // u_i = C[i1][j*] - v[j*]
            double vsel = (tt == 0) ? vreg[0] : (tt == 1) ? vreg[1]
                        : (tt == 2) ? vreg[2] : vreg[3];
            double vj = __shfl_sync(0xffffffffu, vsel, sl);
            double ui = (double)Cf[i1 * NGEN + jmin] - vj;

            // relax unscanned columns
            #pragma unroll
            for (int t = 0; t < 4; t++) {
                if (!((scan >> t) & 1u)) {
                    int j = lane + 32 * t;
                    double nd = mu + ((double)Cf[i1 * NGEN + j] - vreg[t]) - ui;
                    if (dkey(nd) < dkey(dreg[t])) { dreg[t] = nd; pr[t] = i1; }
                }
            }
        }

        // deferred potential update over scanned columns
        #pragma unroll
        for (int t = 0; t < 4; t++)
            if ((scan >> t) & 1u) vreg[t] += dreg[t] - mu;

        // augment along pred chain (warp-collective: shfl fetches pred)
        int j = jmin;
        while (true) {
            const int tt = j >> 5, sl = j & 31;
            int psel = (tt == 0) ? pr[0] : (tt == 1) ? pr[1]
                     : (tt == 2) ? pr[2] : pr[3];
            int i = __shfl_sync(0xffffffffu, psel, sl);
            int jn = 0;
            if (lane == 0) {
                y[j] = i;
                jn = (i == f) ? -1 : x[i];
                x[i] = j;
            }
            jn = __shfl_sync(0xffffffffu, jn, 0);
            if (i == f) break;
            j = jn;
        }
        __syncwarp();
    }

    // transposed return: col[i] = x[i]; order = argsort(col)
    if (lane < G) {
        int c = x[lane];
        int rank = 0;
        #pragma unroll
        for (int r2 = 0; r2 < G; r2++) rank += (x[r2] < c) ? 1 : 0;
        rows_out[b * G + rank] = (float)c;
        cols_out[b * G + rank] = (float)lane;
    }
}

// ---------------------------------------------------------------------------
// Launch
// ---------------------------------------------------------------------------
extern "C" void kernel_launch(void* const* d_in, const int* in_sizes, int n_in,
                              void* d_out, int out_size) {
    const float* prel = (const float*)d_in[0];
    Ptrs ptrs;
    for (int d = 0; d < 8; d++) ptrs.pos[d]  = (const float*)d_in[1 + d];
    const int* grel = (const int*)d_in[9];
    for (int d = 0; d < 8; d++) ptrs.gidx[d] = (const int*)d_in[10 + d];

    float* out = (float*)d_out;

    cost_kernel<<<BSZ * NGEN, 256>>>(prel, grel, ptrs, out);

    float* rows_out = out + COST_ELEMS;
    float* cols_out = rows_out + (size_t)BSZ * G;
    lsa_kernel<<<BSZ, 32>>>(out, rows_out, cols_out);
}